// round 7
// baseline (speedup 1.0000x reference)
#include <cuda_runtime.h>

// ---------------------------------------------------------------------------
// GAT, B=32 N=14 IN=OUT=1024 H=4.
//  k1 : Wh partial GEMM (k-split 2) + a-dot partials. 256 CTAs, occ 2.
//  k1b: softmax + h_prime, split by col-half, writes h_prime TRANSPOSED.
//  k2 : out partials = h_prime @ fc_w^T. 8o x 8b thread tile, dup'd hp smem,
//       512 CTAs x 128 thr, occ 4, double-buffered.
//  k3a: reduce 128 partials + bias. k3b: log_softmax.
// ---------------------------------------------------------------------------

#define NEGC -9e15f

__device__ __forceinline__ float2 ffma2(float2 a, float2 b, float2 c) {
    float2 d;
    asm("fma.rn.f32x2 %0, %1, %2, %3;"
        : "=l"(*reinterpret_cast<unsigned long long*>(&d))
        : "l"(*reinterpret_cast<unsigned long long*>(&a)),
          "l"(*reinterpret_cast<unsigned long long*>(&b)),
          "l"(*reinterpret_cast<unsigned long long*>(&c)));
    return d;
}

// scratch
__device__ float g_whp[2][128 * 14 * 1024];    // Wh k-partials
__device__ float g_dotp[2][128 * 28];          // a-dot k-partials
__device__ float g_hpT[4 * 14336 * 32];        // h_prime transposed (h, f, b)
__device__ float g_part[128 * 32 * 1024];      // out partials (h*32+ks, b, o)
__device__ float g_red[32 * 1024];             // reduced logits

// ---------------------------------------------------------------------------
// k1: grid 256 = hb*2 + kh. 256 threads, 4 cols/thread, K-half 512.
// ---------------------------------------------------------------------------
__global__ __launch_bounds__(256, 2) void k1(
    const float* __restrict__ x, const float* __restrict__ W,
    const float* __restrict__ a)
{
    extern __shared__ float s_x[];              // [ii*16 + n], 32 KB
    __shared__ float s_red[8][28];

    const int tid = threadIdx.x;
    const int hb  = blockIdx.x >> 1;
    const int kh  = blockIdx.x & 1;
    const int b   = hb & 31;
    const int k0  = kh << 9;
    const int c0  = tid * 4;
    const int wid = tid >> 5, lane = tid & 31;

    // stage x[b][n][k0..k0+511] transposed
    const float* xb = x + (size_t)b * 14336 + k0;
    for (int idx = tid; idx < 7168; idx += 256) {
        int n = idx >> 9, ii = idx & 511;
        s_x[ii * 16 + n] = xb[n * 1024 + ii];
    }
    __syncthreads();

    const float4* W4 = (const float4*)(W + ((size_t)hb << 20) + ((size_t)k0 << 10));

    float2 acc[7][4];
    #pragma unroll
    for (int p = 0; p < 7; p++)
        #pragma unroll
        for (int c = 0; c < 4; c++) acc[p][c] = make_float2(0.f, 0.f);

    float4 wc[4];
    #pragma unroll
    for (int u = 0; u < 4; u++) wc[u] = W4[(size_t)u * 256 + tid];

    #pragma unroll 1
    for (int k = 0; k < 512; k += 4) {
        float4 wn[4];
        if (k + 4 < 512) {
            #pragma unroll
            for (int u = 0; u < 4; u++)
                wn[u] = W4[(size_t)(k + 4 + u) * 256 + tid];
        }
        #pragma unroll
        for (int u = 0; u < 4; u++) {
            const float* xr = &s_x[(k + u) * 16];
            float4 xa = *(const float4*)(xr);
            float4 xb4 = *(const float4*)(xr + 4);
            float4 xc = *(const float4*)(xr + 8);
            float2 xd = *(const float2*)(xr + 12);
            float2 xp[7];
            xp[0] = make_float2(xa.x, xa.y);   xp[1] = make_float2(xa.z, xa.w);
            xp[2] = make_float2(xb4.x, xb4.y); xp[3] = make_float2(xb4.z, xb4.w);
            xp[4] = make_float2(xc.x, xc.y);   xp[5] = make_float2(xc.z, xc.w);
            xp[6] = xd;
            float2 s0 = make_float2(wc[u].x, wc[u].x);
            float2 s1 = make_float2(wc[u].y, wc[u].y);
            float2 s2 = make_float2(wc[u].z, wc[u].z);
            float2 s3 = make_float2(wc[u].w, wc[u].w);
            #pragma unroll
            for (int p = 0; p < 7; p++) {
                acc[p][0] = ffma2(xp[p], s0, acc[p][0]);
                acc[p][1] = ffma2(xp[p], s1, acc[p][1]);
                acc[p][2] = ffma2(xp[p], s2, acc[p][2]);
                acc[p][3] = ffma2(xp[p], s3, acc[p][3]);
            }
        }
        #pragma unroll
        for (int u = 0; u < 4; u++) wc[u] = wn[u];
    }

    // write Wh partial
    float* dst = g_whp[kh] + (size_t)hb * 14336 + c0;
    #pragma unroll
    for (int p = 0; p < 7; p++) {
        *(float4*)(dst + (size_t)(2 * p) * 1024) =
            make_float4(acc[p][0].x, acc[p][1].x, acc[p][2].x, acc[p][3].x);
        *(float4*)(dst + (size_t)(2 * p + 1) * 1024) =
            make_float4(acc[p][0].y, acc[p][1].y, acc[p][2].y, acc[p][3].y);
    }

    // a-dot partials over this thread's 4 cols (valid on k-partials: linear)
    float4 a1 = *(const float4*)(a + (size_t)hb * 2048 + c0);
    float4 a2 = *(const float4*)(a + (size_t)hb * 2048 + 1024 + c0);
    float s1[14], s2[14];
    #pragma unroll
    for (int p = 0; p < 7; p++) {
        s1[2*p]   = acc[p][0].x*a1.x + acc[p][1].x*a1.y + acc[p][2].x*a1.z + acc[p][3].x*a1.w;
        s1[2*p+1] = acc[p][0].y*a1.x + acc[p][1].y*a1.y + acc[p][2].y*a1.z + acc[p][3].y*a1.w;
        s2[2*p]   = acc[p][0].x*a2.x + acc[p][1].x*a2.y + acc[p][2].x*a2.z + acc[p][3].x*a2.w;
        s2[2*p+1] = acc[p][0].y*a2.x + acc[p][1].y*a2.y + acc[p][2].y*a2.z + acc[p][3].y*a2.w;
    }
    #pragma unroll
    for (int n = 0; n < 14; n++) {
        #pragma unroll
        for (int off = 16; off > 0; off >>= 1) {
            s1[n] += __shfl_down_sync(0xFFFFFFFFu, s1[n], off);
            s2[n] += __shfl_down_sync(0xFFFFFFFFu, s2[n], off);
        }
    }
    if (lane == 0) {
        #pragma unroll
        for (int n = 0; n < 14; n++) { s_red[wid][n] = s1[n]; s_red[wid][14 + n] = s2[n]; }
    }
    __syncthreads();
    if (tid < 28) {
        float s = 0.f;
        #pragma unroll
        for (int w = 0; w < 8; w++) s += s_red[w][tid];
        g_dotp[kh][hb * 28 + tid] = s;
    }
}

// ---------------------------------------------------------------------------
// k1b: grid 256 = hb*2 + ch. 256 threads, 2 cols/thread.
// softmax (redundant per CTA, tiny) + h_prime slice -> g_hpT transposed.
// ---------------------------------------------------------------------------
__global__ __launch_bounds__(256, 2) void k1b(const float* __restrict__ adj)
{
    __shared__ float s_dot[28];
    __shared__ float s_att[14 * 16];

    const int tid = threadIdx.x;
    const int hb  = blockIdx.x >> 1;
    const int ch  = blockIdx.x & 1;
    const int b   = hb & 31;
    const int h   = hb >> 5;
    const int c0  = ch * 512 + tid * 2;

    if (tid < 28)
        s_dot[tid] = g_dotp[0][hb * 28 + tid] + g_dotp[1][hb * 28 + tid];
    __syncthreads();

    if (tid < 196) {
        int n = tid / 14, m = tid - n * 14;
        float e = s_dot[n] + s_dot[14 + m];
        e = (e > 0.f) ? e : 0.2f * e;
        float ad = adj[b * 196 + n * 14 + m];
        s_att[m * 16 + n] = (ad > 0.f) ? e : NEGC;
    }
    __syncthreads();

    if (tid < 14) {
        const int m = tid;
        float mx = -3.4e38f, ev[14], s = 0.f;
        #pragma unroll
        for (int n = 0; n < 14; n++) mx = fmaxf(mx, s_att[m * 16 + n]);
        #pragma unroll
        for (int n = 0; n < 14; n++) { ev[n] = expf(s_att[m * 16 + n] - mx); s += ev[n]; }
        float inv = 1.f / s;
        #pragma unroll
        for (int n = 0; n < 14; n++) s_att[m * 16 + n] = ev[n] * inv;
    }
    __syncthreads();

    // Wh slice (sum of k-partials)
    float2 wh[14];
    const float* p0 = g_whp[0] + (size_t)hb * 14336 + c0;
    const float* p1 = g_whp[1] + (size_t)hb * 14336 + c0;
    #pragma unroll
    for (int m = 0; m < 14; m++) {
        float2 v0 = *(const float2*)(p0 + m * 1024);
        float2 v1 = *(const float2*)(p1 + m * 1024);
        wh[m] = make_float2(v0.x + v1.x, v0.y + v1.y);
    }

    float2 hp[14];
    #pragma unroll
    for (int n = 0; n < 14; n++) hp[n] = make_float2(0.f, 0.f);
    #pragma unroll
    for (int m = 0; m < 14; m++) {
        float wx = wh[m].x, wy = wh[m].y;
        #pragma unroll
        for (int n = 0; n < 14; n++) {
            float at = s_att[m * 16 + n];
            hp[n].x = fmaf(at, wx, hp[n].x);
            hp[n].y = fmaf(at, wy, hp[n].y);
        }
    }

    // write transposed: g_hpT[(h*14336 + f) * 32 + b]
    #pragma unroll
    for (int n = 0; n < 14; n++) {
        size_t f = (size_t)h * 14336 + n * 1024 + c0;
        g_hpT[f * 32 + b]       = hp[n].x;
        g_hpT[(f + 1) * 32 + b] = hp[n].y;
    }
}

// ---------------------------------------------------------------------------
// k2: grid (ks=32, ot=4, h=4) = 512 CTAs, 128 threads, occ 4.
// CTA: 256 o x 32 b, k-span 448, chunk 8. Thread: 8o x 8b.
// s_hp2 holds duplicated pairs (v,v,w,w) so b-broadcast is 1 LDS.128 / 2 b.
// ---------------------------------------------------------------------------
__global__ __launch_bounds__(128, 4) void k2(const float* __restrict__ fcw)
{
    __shared__ float s_w[2][8 * 256];           // [buf][k][o]
    __shared__ float s_hp2[2][8 * 64];          // [buf][k][2b dup]

    const int tid  = threadIdx.x;
    const int lane = tid & 31;
    const int w    = tid >> 5;                  // 0..3 = b-group
    const int ks   = blockIdx.x;
    const int ot   = blockIdx.y;
    const int h    = blockIdx.z;
    const int kbase = ks * 448;
    const int obase = ot * 256;

    const float* wr0 = fcw + ((size_t)(h * 1024 + obase + tid)) * 14336 + kbase;
    const float* wr1 = wr0 + (size_t)128 * 14336;
    const int kk = tid >> 4;                    // 0..7
    const int bp = tid & 15;                    // 0..15
    const float* hpr = g_hpT + ((size_t)(h * 14336 + kbase + kk)) * 32 + 2 * bp;

    float2 acc[4][8];
    #pragma unroll
    for (int q = 0; q < 4; q++)
        #pragma unroll
        for (int j = 0; j < 8; j++) acc[q][j] = make_float2(0.f, 0.f);

    // prologue: stage chunk 0 -> buffer 0
    {
        float4 w0a = *(const float4*)(wr0);
        float4 w0b = *(const float4*)(wr0 + 4);
        float4 w1a = *(const float4*)(wr1);
        float4 w1b = *(const float4*)(wr1 + 4);
        float2 hv  = *(const float2*)(hpr);
        float a0[4] = {w0a.x, w0a.y, w0a.z, w0a.w};
        float b0v[4] = {w0b.x, w0b.y, w0b.z, w0b.w};
        float a1[4] = {w1a.x, w1a.y, w1a.z, w1a.w};
        float b1v[4] = {w1b.x, w1b.y, w1b.z, w1b.w};
        #pragma unroll
        for (int kq = 0; kq < 4; kq++) {
            s_w[0][kq * 256 + tid]             = a0[kq];
            s_w[0][(kq + 4) * 256 + tid]       = b0v[kq];
            s_w[0][kq * 256 + tid + 128]       = a1[kq];
            s_w[0][(kq + 4) * 256 + tid + 128] = b1v[kq];
        }
        *(float4*)&s_hp2[0][kk * 64 + 4 * bp] = make_float4(hv.x, hv.x, hv.y, hv.y);
    }
    __syncthreads();

    #pragma unroll 1
    for (int ck = 0; ck < 56; ck++) {
        const int buf = ck & 1;

        float4 w0a, w0b, w1a, w1b; float2 hv;
        if (ck + 1 < 56) {
            const int ko = (ck + 1) * 8;
            w0a = *(const float4*)(wr0 + ko);
            w0b = *(const float4*)(wr0 + ko + 4);
            w1a = *(const float4*)(wr1 + ko);
            w1b = *(const float4*)(wr1 + ko + 4);
            hv  = *(const float2*)(hpr + (size_t)(ck + 1) * 256);
        }

        #pragma unroll
        for (int k = 0; k < 8; k++) {
            float2 af[4];
            #pragma unroll
            for (int q = 0; q < 4; q++)
                af[q] = *(const float2*)&s_w[buf][k * 256 + 2 * lane + 64 * q];
            float4 bq[4];
            #pragma unroll
            for (int j = 0; j < 4; j++)
                bq[j] = *(const float4*)&s_hp2[buf][k * 64 + w * 16 + 4 * j];
            #pragma unroll
            for (int q = 0; q < 4; q++) {
                acc[q][0] = ffma2(af[q], make_float2(bq[0].x, bq[0].y), acc[q][0]);
                acc[q][1] = ffma2(af[q], make_float2(bq[0].z, bq[0].w), acc[q][1]);
                acc[q][2] = ffma2(af[q], make_float2(bq[1].x, bq[1].y), acc[q][2]);
                acc[q][3] = ffma2(af[q], make_float2(bq[1].z, bq[1].w), acc[q][3]);
                acc[q][4] = ffma2(af[q], make_float2(bq[2].x, bq[2].y), acc[q][4]);
                acc[q][5] = ffma2(af[q], make_float2(bq[2].z, bq[2].w), acc[q][5]);
                acc[q][6] = ffma2(af[q], make_float2(bq[3].x, bq[3].y), acc[q][6]);
                acc[q][7] = ffma2(af[q], make_float2(bq[3].z, bq[3].w), acc[q][7]);
            }
        }

        if (ck + 1 < 56) {
            const int nb = buf ^ 1;
            float a0[4] = {w0a.x, w0a.y, w0a.z, w0a.w};
            float b0v[4] = {w0b.x, w0b.y, w0b.z, w0b.w};
            float a1[4] = {w1a.x, w1a.y, w1a.z, w1a.w};
            float b1v[4] = {w1b.x, w1b.y, w1b.z, w1b.w};
            #pragma unroll
            for (int kq = 0; kq < 4; kq++) {
                s_w[nb][kq * 256 + tid]             = a0[kq];
                s_w[nb][(kq + 4) * 256 + tid]       = b0v[kq];
                s_w[nb][kq * 256 + tid + 128]       = a1[kq];
                s_w[nb][(kq + 4) * 256 + tid + 128] = b1v[kq];
            }
            *(float4*)&s_hp2[nb][kk * 64 + 4 * bp] = make_float4(hv.x, hv.x, hv.y, hv.y);
            __syncthreads();
        }
    }

    float* dst = g_part + ((size_t)(h * 32 + ks)) * 32768 + obase;
    #pragma unroll
    for (int j = 0; j < 8; j++)
        #pragma unroll
        for (int q = 0; q < 4; q++)
            *(float2*)(dst + (size_t)(w * 8 + j) * 1024 + 2 * lane + 64 * q) = acc[q][j];
}

// ---------------------------------------------------------------------------
// k3a: reduce 128 partials + bias. grid 256 (= b*8 + oc), 128 threads.
// ---------------------------------------------------------------------------
__global__ __launch_bounds__(128, 8) void k3a(const float* __restrict__ fcb)
{
    const int b = blockIdx.x >> 3;
    const int o = (blockIdx.x & 7) * 128 + threadIdx.x;

    const float* p = g_part + b * 1024 + o;
    float s0 = 0.f, s1 = 0.f, s2 = 0.f, s3 = 0.f;
    #pragma unroll 8
    for (int pb = 0; pb < 128; pb += 4) {
        s0 += p[(size_t)pb * 32768];
        s1 += p[(size_t)(pb + 1) * 32768];
        s2 += p[(size_t)(pb + 2) * 32768];
        s3 += p[(size_t)(pb + 3) * 32768];
    }
    float s = (s0 + s1) + (s2 + s3)
            + fcb[o] + fcb[1024 + o] + fcb[2048 + o] + fcb[3072 + o];
    g_red[b * 1024 + o] = s;
}

// ---------------------------------------------------------------------------
// k3b: log_softmax per b. grid 32, 256 threads.
// ---------------------------------------------------------------------------
__global__ __launch_bounds__(256, 1) void k3b(float* __restrict__ out)
{
    __shared__ float red[256];
    const int b = blockIdx.x, tid = threadIdx.x;

    float4 v = *(const float4*)&g_red[b * 1024 + tid * 4];

    float mx = fmaxf(fmaxf(v.x, v.y), fmaxf(v.z, v.w));
    red[tid] = mx; __syncthreads();
    for (int st = 128; st > 0; st >>= 1) {
        if (tid < st) red[tid] = fmaxf(red[tid], red[tid + st]);
        __syncthreads();
    }
    mx = red[0]; __syncthreads();

    float s = expf(v.x - mx) + expf(v.y - mx) + expf(v.z - mx) + expf(v.w - mx);
    red[tid] = s; __syncthreads();
    for (int st = 128; st > 0; st >>= 1) {
        if (tid < st) red[tid] += red[tid + st];
        __syncthreads();
    }
    float lse = mx + logf(red[0]);

    *(float4*)&out[b * 1024 + tid * 4] =
        make_float4(v.x - lse, v.y - lse, v.z - lse, v.w - lse);
}

// ---------------------------------------------------------------------------
extern "C" void kernel_launch(void* const* d_in, const int* in_sizes, int n_in,
                              void* d_out, int out_size)
{
    const float *x = nullptr, *adj = nullptr, *W = nullptr, *a = nullptr,
                *fcw = nullptr, *fcb = nullptr;
    for (int i = 0; i < n_in; i++) {
        switch (in_sizes[i]) {
            case 32 * 14 * 1024:        x   = (const float*)d_in[i]; break;
            case 32 * 14 * 14:          adj = (const float*)d_in[i]; break;
            case 4 * 32 * 1024 * 1024:  W   = (const float*)d_in[i]; break;
            case 4 * 32 * 2048:         a   = (const float*)d_in[i]; break;
            case 4 * 1024 * 14336:      fcw = (const float*)d_in[i]; break;
            case 4 * 1024:              fcb = (const float*)d_in[i]; break;
            default: break;
        }
    }
    float* out = (float*)d_out;

    k1<<<256, 256, 32768>>>(x, W, a);
    k1b<<<256, 256>>>(adj);
    k2<<<dim3(32, 4, 4), 128>>>(fcw);
    k3a<<<256, 128>>>(fcb);
    k3b<<<32, 256>>>(out);
}

// round 8
// speedup vs baseline: 1.0465x; 1.0465x over previous
#include <cuda_runtime.h>

// ---------------------------------------------------------------------------
// GAT, B=32 N=14 IN=OUT=1024 H=4.
//  k1 : Wh partial GEMM (k-split 2), 4 cols/thread, LDG.128, 2-chunk register
//       ring prefetch, fused a-dot partials. 256 CTAs, occ 2.
//  k1b: softmax + h_prime, col-half split (256 CTAs), row-major g_hp.
//  k2 : out partials = h_prime @ fc_w^T, double-buffered smem GEMM (round-6).
//  k3a: reduce 64 partials + bias. k3b: log_softmax.
// ---------------------------------------------------------------------------

#define NEGC -9e15f

__device__ __forceinline__ float2 ffma2(float2 a, float2 b, float2 c) {
    float2 d;
    asm("fma.rn.f32x2 %0, %1, %2, %3;"
        : "=l"(*reinterpret_cast<unsigned long long*>(&d))
        : "l"(*reinterpret_cast<unsigned long long*>(&a)),
          "l"(*reinterpret_cast<unsigned long long*>(&b)),
          "l"(*reinterpret_cast<unsigned long long*>(&c)));
    return d;
}

// scratch
__device__ float g_whp[2][128 * 14 * 1024];    // Wh k-partials
__device__ float g_dotp[2][128 * 28];          // a-dot k-partials
__device__ float g_hp[128 * 14 * 1024];        // h_prime (hb, n, c)
__device__ float g_part[64 * 32 * 1024];       // out partials (h*16+ks, b, o)
__device__ float g_red[32 * 1024];             // reduced logits

// ---------------------------------------------------------------------------
// k1: grid 256 = hb*2 + kh. 256 threads, 4 cols/thread, K-half 512.
// ---------------------------------------------------------------------------
__global__ __launch_bounds__(256, 2) void k1(
    const float* __restrict__ x, const float* __restrict__ W,
    const float* __restrict__ a)
{
    __shared__ float s_x[512 * 16];             // [ii*16 + n], 32 KB
    __shared__ float s_red[8][28];

    const int tid = threadIdx.x;
    const int hb  = blockIdx.x >> 1;
    const int kh  = blockIdx.x & 1;
    const int b   = hb & 31;
    const int k0  = kh << 9;
    const int c0  = tid * 4;
    const int wid = tid >> 5, lane = tid & 31;

    // stage x[b][n][k0..k0+511] transposed
    const float* xb = x + (size_t)b * 14336 + k0;
    for (int idx = tid; idx < 7168; idx += 256) {
        int n = idx >> 9, ii = idx & 511;
        s_x[ii * 16 + n] = xb[n * 1024 + ii];
    }
    __syncthreads();

    const float4* W4 = (const float4*)(W + ((size_t)hb << 20) + ((size_t)k0 << 10));

    float2 acc[7][4];
    #pragma unroll
    for (int p = 0; p < 7; p++)
        #pragma unroll
        for (int c = 0; c < 4; c++) acc[p][c] = make_float2(0.f, 0.f);

    float4 bufA[4], bufB[4];
    #pragma unroll
    for (int u = 0; u < 4; u++) bufA[u] = W4[(size_t)u * 256 + tid];
    #pragma unroll
    for (int u = 0; u < 4; u++) bufB[u] = W4[(size_t)(4 + u) * 256 + tid];

    // compute 4 consecutive k's from a register buffer
    auto comp4 = [&](const float4* buf, int kk) {
        #pragma unroll
        for (int u = 0; u < 4; u++) {
            const float* xr = &s_x[(kk + u) * 16];
            float4 xa  = *(const float4*)(xr);
            float4 xb4 = *(const float4*)(xr + 4);
            float4 xc  = *(const float4*)(xr + 8);
            float2 xd  = *(const float2*)(xr + 12);
            float2 xp[7];
            xp[0] = make_float2(xa.x, xa.y);   xp[1] = make_float2(xa.z, xa.w);
            xp[2] = make_float2(xb4.x, xb4.y); xp[3] = make_float2(xb4.z, xb4.w);
            xp[4] = make_float2(xc.x, xc.y);   xp[5] = make_float2(xc.z, xc.w);
            xp[6] = xd;
            float2 s0 = make_float2(buf[u].x, buf[u].x);
            float2 s1 = make_float2(buf[u].y, buf[u].y);
            float2 s2 = make_float2(buf[u].z, buf[u].z);
            float2 s3 = make_float2(buf[u].w, buf[u].w);
            #pragma unroll
            for (int p = 0; p < 7; p++) {
                acc[p][0] = ffma2(xp[p], s0, acc[p][0]);
                acc[p][1] = ffma2(xp[p], s1, acc[p][1]);
                acc[p][2] = ffma2(xp[p], s2, acc[p][2]);
                acc[p][3] = ffma2(xp[p], s3, acc[p][3]);
            }
        }
    };

    #pragma unroll 1
    for (int k = 0; k < 512; k += 8) {
        comp4(bufA, k);
        if (k + 8 < 512) {
            #pragma unroll
            for (int u = 0; u < 4; u++)
                bufA[u] = W4[(size_t)(k + 8 + u) * 256 + tid];
        }
        comp4(bufB, k + 4);
        if (k + 12 < 512) {
            #pragma unroll
            for (int u = 0; u < 4; u++)
                bufB[u] = W4[(size_t)(k + 12 + u) * 256 + tid];
        }
    }

    // write Wh partial
    float* dst = g_whp[kh] + (size_t)hb * 14336 + c0;
    #pragma unroll
    for (int p = 0; p < 7; p++) {
        *(float4*)(dst + (size_t)(2 * p) * 1024) =
            make_float4(acc[p][0].x, acc[p][1].x, acc[p][2].x, acc[p][3].x);
        *(float4*)(dst + (size_t)(2 * p + 1) * 1024) =
            make_float4(acc[p][0].y, acc[p][1].y, acc[p][2].y, acc[p][3].y);
    }

    // a-dot partials (linear in Wh => valid on k-partials)
    float4 a1 = *(const float4*)(a + (size_t)hb * 2048 + c0);
    float4 a2 = *(const float4*)(a + (size_t)hb * 2048 + 1024 + c0);
    float s1[14], s2[14];
    #pragma unroll
    for (int p = 0; p < 7; p++) {
        s1[2*p]   = acc[p][0].x*a1.x + acc[p][1].x*a1.y + acc[p][2].x*a1.z + acc[p][3].x*a1.w;
        s1[2*p+1] = acc[p][0].y*a1.x + acc[p][1].y*a1.y + acc[p][2].y*a1.z + acc[p][3].y*a1.w;
        s2[2*p]   = acc[p][0].x*a2.x + acc[p][1].x*a2.y + acc[p][2].x*a2.z + acc[p][3].x*a2.w;
        s2[2*p+1] = acc[p][0].y*a2.x + acc[p][1].y*a2.y + acc[p][2].y*a2.z + acc[p][3].y*a2.w;
    }
    #pragma unroll
    for (int n = 0; n < 14; n++) {
        #pragma unroll
        for (int off = 16; off > 0; off >>= 1) {
            s1[n] += __shfl_down_sync(0xFFFFFFFFu, s1[n], off);
            s2[n] += __shfl_down_sync(0xFFFFFFFFu, s2[n], off);
        }
    }
    if (lane == 0) {
        #pragma unroll
        for (int n = 0; n < 14; n++) { s_red[wid][n] = s1[n]; s_red[wid][14 + n] = s2[n]; }
    }
    __syncthreads();
    if (tid < 28) {
        float s = 0.f;
        #pragma unroll
        for (int w = 0; w < 8; w++) s += s_red[w][tid];
        g_dotp[kh][hb * 28 + tid] = s;
    }
}

// ---------------------------------------------------------------------------
// k1b: grid 256 = hb*2 + ch. 256 threads, 2 cols/thread.
// softmax (redundant per CTA, tiny) + h_prime slice -> g_hp (row-major).
// ---------------------------------------------------------------------------
__global__ __launch_bounds__(256, 2) void k1b(const float* __restrict__ adj)
{
    __shared__ float s_dot[28];
    __shared__ float s_att[14 * 16];

    const int tid = threadIdx.x;
    const int hb  = blockIdx.x >> 1;
    const int ch  = blockIdx.x & 1;
    const int b   = hb & 31;
    const int c0  = ch * 512 + tid * 2;

    if (tid < 28)
        s_dot[tid] = g_dotp[0][hb * 28 + tid] + g_dotp[1][hb * 28 + tid];
    __syncthreads();

    if (tid < 196) {
        int n = tid / 14, m = tid - n * 14;
        float e = s_dot[n] + s_dot[14 + m];
        e = (e > 0.f) ? e : 0.2f * e;
        float ad = adj[b * 196 + n * 14 + m];
        s_att[m * 16 + n] = (ad > 0.f) ? e : NEGC;
    }
    __syncthreads();

    if (tid < 14) {
        const int m = tid;
        float mx = -3.4e38f, ev[14], s = 0.f;
        #pragma unroll
        for (int n = 0; n < 14; n++) mx = fmaxf(mx, s_att[m * 16 + n]);
        #pragma unroll
        for (int n = 0; n < 14; n++) { ev[n] = expf(s_att[m * 16 + n] - mx); s += ev[n]; }
        float inv = 1.f / s;
        #pragma unroll
        for (int n = 0; n < 14; n++) s_att[m * 16 + n] = ev[n] * inv;
    }
    __syncthreads();

    // Wh slice (sum of k-partials)
    float2 wh[14];
    const float* p0 = g_whp[0] + (size_t)hb * 14336 + c0;
    const float* p1 = g_whp[1] + (size_t)hb * 14336 + c0;
    #pragma unroll
    for (int m = 0; m < 14; m++) {
        float2 v0 = *(const float2*)(p0 + m * 1024);
        float2 v1 = *(const float2*)(p1 + m * 1024);
        wh[m] = make_float2(v0.x + v1.x, v0.y + v1.y);
    }

    float2 hp[14];
    #pragma unroll
    for (int n = 0; n < 14; n++) hp[n] = make_float2(0.f, 0.f);
    #pragma unroll
    for (int m = 0; m < 14; m++) {
        float wx = wh[m].x, wy = wh[m].y;
        #pragma unroll
        for (int n = 0; n < 14; n++) {
            float at = s_att[m * 16 + n];
            hp[n].x = fmaf(at, wx, hp[n].x);
            hp[n].y = fmaf(at, wy, hp[n].y);
        }
    }

    float* hpg = g_hp + (size_t)hb * 14336 + c0;
    #pragma unroll
    for (int n = 0; n < 14; n++)
        *(float2*)(hpg + (size_t)n * 1024) = hp[n];
}

// ---------------------------------------------------------------------------
// k2: double-buffered smem GEMM (round-6). C[256 o x 32 b] per CTA, k-split 16.
// grid (64, 4). One barrier per k-chunk.
// ---------------------------------------------------------------------------
__global__ __launch_bounds__(256, 2) void k2(const float* __restrict__ fcw)
{
    __shared__ float s_w[2][32 * 256];          // [buf][k][o]
    __shared__ float s_hp[2][32 * 32];          // [buf][k][b]

    const int tid = threadIdx.x;
    const int ks  = blockIdx.x >> 2;
    const int ot  = blockIdx.x & 3;
    const int h   = blockIdx.y;
    const int obase = ot * 256;
    const int kbase = ks * 896;

    const int to = tid & 31;
    const int b0 = (tid >> 5) * 4;

    const float* wrow = fcw + ((size_t)(h * 1024 + obase + tid)) * 14336 + kbase;
    const int hb_row = tid >> 3;
    const int kk0 = (tid & 7) * 4;
    const float* hprow = g_hp + ((size_t)(h * 32 + hb_row)) * 14336 + kbase + kk0;

    float2 acc[4][4];
    #pragma unroll
    for (int q = 0; q < 4; q++)
        #pragma unroll
        for (int j = 0; j < 4; j++) acc[q][j] = make_float2(0.f, 0.f);

    // prologue: stage chunk 0 into buffer 0
    {
        float4 vw[8];
        #pragma unroll
        for (int q = 0; q < 8; q++) vw[q] = *(const float4*)(wrow + q * 4);
        float4 vhp = *(const float4*)(hprow);
        #pragma unroll
        for (int q = 0; q < 8; q++) {
            s_w[0][(4 * q + 0) * 256 + tid] = vw[q].x;
            s_w[0][(4 * q + 1) * 256 + tid] = vw[q].y;
            s_w[0][(4 * q + 2) * 256 + tid] = vw[q].z;
            s_w[0][(4 * q + 3) * 256 + tid] = vw[q].w;
        }
        s_hp[0][(kk0 + 0) * 32 + hb_row] = vhp.x;
        s_hp[0][(kk0 + 1) * 32 + hb_row] = vhp.y;
        s_hp[0][(kk0 + 2) * 32 + hb_row] = vhp.z;
        s_hp[0][(kk0 + 3) * 32 + hb_row] = vhp.w;
    }
    __syncthreads();

    #pragma unroll 1
    for (int ck = 0; ck < 28; ck++) {
        const int buf = ck & 1;

        float4 vw[8]; float4 vhp;
        if (ck + 1 < 28) {
            const float* wn = wrow + (ck + 1) * 32;
            #pragma unroll
            for (int q = 0; q < 8; q++) vw[q] = *(const float4*)(wn + q * 4);
            vhp = *(const float4*)(hprow + (ck + 1) * 32);
        }

        #pragma unroll 8
        for (int k = 0; k < 32; k++) {
            float2 af[4];
            #pragma unroll
            for (int q = 0; q < 4; q++)
                af[q] = *(const float2*)&s_w[buf][k * 256 + 2 * to + 64 * q];
            float4 bf = *(const float4*)&s_hp[buf][k * 32 + b0];
            float2 d0 = make_float2(bf.x, bf.x);
            float2 d1 = make_float2(bf.y, bf.y);
            float2 d2 = make_float2(bf.z, bf.z);
            float2 d3 = make_float2(bf.w, bf.w);
            #pragma unroll
            for (int q = 0; q < 4; q++) {
                acc[q][0] = ffma2(af[q], d0, acc[q][0]);
                acc[q][1] = ffma2(af[q], d1, acc[q][1]);
                acc[q][2] = ffma2(af[q], d2, acc[q][2]);
                acc[q][3] = ffma2(af[q], d3, acc[q][3]);
            }
        }

        if (ck + 1 < 28) {
            const int nb = buf ^ 1;
            #pragma unroll
            for (int q = 0; q < 8; q++) {
                s_w[nb][(4 * q + 0) * 256 + tid] = vw[q].x;
                s_w[nb][(4 * q + 1) * 256 + tid] = vw[q].y;
                s_w[nb][(4 * q + 2) * 256 + tid] = vw[q].z;
                s_w[nb][(4 * q + 3) * 256 + tid] = vw[q].w;
            }
            s_hp[nb][(kk0 + 0) * 32 + hb_row] = vhp.x;
            s_hp[nb][(kk0 + 1) * 32 + hb_row] = vhp.y;
            s_hp[nb][(kk0 + 2) * 32 + hb_row] = vhp.z;
            s_hp[nb][(kk0 + 3) * 32 + hb_row] = vhp.w;
            __syncthreads();
        }
    }

    float* dst = g_part + ((size_t)(h * 16 + ks)) * 32768;
    #pragma unroll
    for (int j = 0; j < 4; j++)
        #pragma unroll
        for (int q = 0; q < 4; q++)
            *(float2*)(dst + (size_t)(b0 + j) * 1024 + obase + 2 * to + 64 * q) = acc[q][j];
}

// ---------------------------------------------------------------------------
// k3a: reduce 64 partials + bias. grid 256 (= b*8 + oc), 128 threads.
// ---------------------------------------------------------------------------
__global__ __launch_bounds__(128, 8) void k3a(const float* __restrict__ fcb)
{
    const int b  = blockIdx.x >> 3;
    const int o  = (blockIdx.x & 7) * 128 + threadIdx.x;

    float s = 0.f;
    #pragma unroll 8
    for (int pb = 0; pb < 64; pb++)
        s += g_part[(size_t)pb * 32768 + b * 1024 + o];
    #pragma unroll
    for (int hh = 0; hh < 4; hh++) s += fcb[hh * 1024 + o];
    g_red[b * 1024 + o] = s;
}

// ---------------------------------------------------------------------------
// k3b: log_softmax per b. grid 32, 256 threads.
// ---------------------------------------------------------------------------
__global__ __launch_bounds__(256, 1) void k3b(float* __restrict__ out)
{
    __shared__ float red[256];
    const int b = blockIdx.x, tid = threadIdx.x;

    float4 v = *(const float4*)&g_red[b * 1024 + tid * 4];

    float mx = fmaxf(fmaxf(v.x, v.y), fmaxf(v.z, v.w));
    red[tid] = mx; __syncthreads();
    for (int st = 128; st > 0; st >>= 1) {
        if (tid < st) red[tid] = fmaxf(red[tid], red[tid + st]);
        __syncthreads();
    }
    mx = red[0]; __syncthreads();

    float s = expf(v.x - mx) + expf(v.y - mx) + expf(v.z - mx) + expf(v.w - mx);
    red[tid] = s; __syncthreads();
    for (int st = 128; st > 0; st >>= 1) {
        if (tid < st) red[tid] += red[tid + st];
        __syncthreads();
    }
    float lse = mx + logf(red[0]);

    *(float4*)&out[b * 1024 + tid * 4] =
        make_float4(v.x - lse, v.y - lse, v.z - lse, v.w - lse);
}

// ---------------------------------------------------------------------------
extern "C" void kernel_launch(void* const* d_in, const int* in_sizes, int n_in,
                              void* d_out, int out_size)
{
    const float *x = nullptr, *adj = nullptr, *W = nullptr, *a = nullptr,
                *fcw = nullptr, *fcb = nullptr;
    for (int i = 0; i < n_in; i++) {
        switch (in_sizes[i]) {
            case 32 * 14 * 1024:        x   = (const float*)d_in[i]; break;
            case 32 * 14 * 14:          adj = (const float*)d_in[i]; break;
            case 4 * 32 * 1024 * 1024:  W   = (const float*)d_in[i]; break;
            case 4 * 32 * 2048:         a   = (const float*)d_in[i]; break;
            case 4 * 1024 * 14336:      fcw = (const float*)d_in[i]; break;
            case 4 * 1024:              fcb = (const float*)d_in[i]; break;
            default: break;
        }
    }
    float* out = (float*)d_out;

    k1<<<256, 256>>>(x, W, a);
    k1b<<<256, 256>>>(adj);
    k2<<<dim3(64, 4), 256>>>(fcw);
    k3a<<<256, 128>>>(fcb);
    k3b<<<32, 256>>>(out);
}